// round 10
// baseline (speedup 1.0000x reference)
#include <cuda_runtime.h>
#include <cuda_bf16.h>
#include <cstdint>

#define N_NODES 50000
#define N_EDGES 600000
#define D_IN    128
#define D_HID   1024
#define D_OUT   128

// ---------------------------------------------------------------------------
// Device-global scratch. ONLY referenced from device code (host-shadow bug).
// ---------------------------------------------------------------------------
__device__ float         g_h[(size_t)N_NODES * D_IN];
__device__ __nv_bfloat16 g_w1t_hi[(size_t)D_HID * D_IN];      // W1^T [1024][128]
__device__ __nv_bfloat16 g_w1t_lo[(size_t)D_HID * D_IN];
__device__ __nv_bfloat16 g_w2t_hi[(size_t)D_OUT * D_HID];     // W2^T [128][1024]
__device__ __nv_bfloat16 g_w2t_lo[(size_t)D_OUT * D_HID];

// ---------------------------------------------------------------------------
// Helpers
// ---------------------------------------------------------------------------
__device__ __forceinline__ uint32_t smem_u32(const void* p) {
    uint32_t a;
    asm("{ .reg .u64 t; cvta.to.shared.u64 t, %1; cvt.u32.u64 %0, t; }" : "=r"(a) : "l"(p));
    return a;
}
#define SW128(x) ((x) ^ (((x) >> 3) & 0x70))

// 128-row x 128-k tile: two 16KB sub-tiles (k-bytes [0,128),[128,256)), SW128.
__device__ __forceinline__ uint32_t toff(int row, int kbyte) {
    uint32_t w = (uint32_t)(row * 128 + (kbyte & 127));
    return (uint32_t)((kbyte >> 7) * 16384) + SW128(w);
}
// W1 half-tile: 64 rows x 128 k -> two 8KB sub-tiles.
__device__ __forceinline__ uint32_t toffW1(int row, int kbyte) {
    uint32_t w = (uint32_t)(row * 128 + (kbyte & 127));
    return (uint32_t)((kbyte >> 7) * 8192) + SW128(w);
}
// W2 half-tile: 128 rows x 64 k -> one 16KB tile (128B per row).
__device__ __forceinline__ uint32_t toffW2(int row, int kbyte) {
    uint32_t w = (uint32_t)(row * 128 + kbyte);
    return SW128(w);
}

__device__ __forceinline__ void ldsm_x4(uint32_t (&r)[4], uint32_t addr) {
    asm volatile("ldmatrix.sync.aligned.m8n8.x4.shared.b16 {%0,%1,%2,%3}, [%4];"
                 : "=r"(r[0]), "=r"(r[1]), "=r"(r[2]), "=r"(r[3]) : "r"(addr));
}
__device__ __forceinline__ void mma_bf16(float (&d)[4], const uint32_t (&a)[4],
                                         uint32_t b0, uint32_t b1) {
    asm volatile(
        "mma.sync.aligned.m16n8k16.row.col.f32.bf16.bf16.f32 "
        "{%0,%1,%2,%3}, {%4,%5,%6,%7}, {%8,%9}, {%0,%1,%2,%3};"
        : "+f"(d[0]), "+f"(d[1]), "+f"(d[2]), "+f"(d[3])
        : "r"(a[0]), "r"(a[1]), "r"(a[2]), "r"(a[3]), "r"(b0), "r"(b1));
}
__device__ __forceinline__ uint32_t pack_bf2(float x0, float x1) {
    __nv_bfloat162 p = __floats2bfloat162_rn(x0, x1);
    return *reinterpret_cast<uint32_t*>(&p);
}
__device__ __forceinline__ void cp16(uint32_t dst, const void* src) {
    asm volatile("cp.async.cg.shared.global [%0], [%1], 16;" :: "r"(dst), "l"(src));
}

// ---------------------------------------------------------------------------
// Phase 1: zero accumulator
// ---------------------------------------------------------------------------
__global__ void zero_h_kernel() {
    int i = blockIdx.x * blockDim.x + threadIdx.x;
    const int n4 = N_NODES * D_IN / 4;
    if (i < n4) reinterpret_cast<float4*>(g_h)[i] = make_float4(0.f, 0.f, 0.f, 0.f);
}

// ---------------------------------------------------------------------------
// Phase 2: scatter (proven). One warp per edge; float4 atomics.
// ---------------------------------------------------------------------------
__global__ void scatter_kernel(const float* __restrict__ feat,
                               const float* __restrict__ edge_feat,
                               const int*   __restrict__ src,
                               const int*   __restrict__ dst) {
    int warp = (blockIdx.x * blockDim.x + threadIdx.x) >> 5;
    int lane = threadIdx.x & 31;
    if (warp >= N_EDGES) return;
    int s = src[warp], d = dst[warp];
    const float4 a = reinterpret_cast<const float4*>(feat      + (size_t)s    * D_IN)[lane];
    const float4 b = reinterpret_cast<const float4*>(edge_feat + (size_t)warp * D_IN)[lane];
    float4 m = make_float4(a.x + b.x, a.y + b.y, a.z + b.z, a.w + b.w);
    atomicAdd(reinterpret_cast<float4*>(g_h + (size_t)d * D_IN + lane * 4), m);
}

// ---------------------------------------------------------------------------
// Phase 3: merged weight transpose + split (one launch).
// ---------------------------------------------------------------------------
__global__ void wsplit_kernel(const float* __restrict__ W1, const float* __restrict__ W2) {
    int b = blockIdx.x;
    if (b < 512) {
        int i = b * 256 + threadIdx.x;               // over W1 [128][1024]
        int k = i >> 10, n = i & 1023;
        float x = W1[i];
        __nv_bfloat16 hi = __float2bfloat16(x);
        g_w1t_hi[(size_t)n * D_IN + k] = hi;
        g_w1t_lo[(size_t)n * D_IN + k] = __float2bfloat16(x - __bfloat162float(hi));
    } else {
        int i = (b - 512) * 256 + threadIdx.x;       // over W2 [1024][128]
        int k = i >> 7, n = i & 127;
        float x = W2[i];
        __nv_bfloat16 hi = __float2bfloat16(x);
        g_w2t_hi[(size_t)n * D_HID + k] = hi;
        g_w2t_lo[(size_t)n * D_HID + k] = __float2bfloat16(x - __bfloat162float(hi));
    }
}

// ---------------------------------------------------------------------------
// Phase 4: cp.async-pipelined fused MLP, 512 threads (16 warps).
// Smem: A(64K) + H(64K) + 3x32K weight ring = 224KB, 1 CTA/SM.
// Stage1 warp layout: 8(M)x2(N), warp tile 16x32.  hacc[4][4] per half.
// Stage2 warp layout: 4(M)x4(N), warp tile 32x32.  oacc[2][4][4].
// ---------------------------------------------------------------------------
#define OFF_A_HI 0
#define OFF_A_LO 32768
#define OFF_H_HI 65536
#define OFF_H_LO 98304
#define OFF_WB   131072      // 3 buffers x 32KB (hi 16K + lo 16K)

__device__ __forceinline__ void load_tile(char* smem, int t, int wq) {
    const int c8 = t >> 2, j = t & 3;
    const int tid = threadIdx.x;
    const uint32_t base = smem_u32(smem) + OFF_WB + wq * 32768;
    if (j < 2) {           // W1 half j: rows c8*128 + j*64 + [0,64), k [0,128)
#pragma unroll
        for (int c = tid; c < 64 * 16; c += 512) {
            int row = c >> 4, ch = c & 15;
            size_t g = (size_t)(c8 * 128 + j * 64 + row) * D_IN + ch * 8;
            uint32_t o = toffW1(row, ch * 16);
            cp16(base + o,         g_w1t_hi + g);
            cp16(base + 16384 + o, g_w1t_lo + g);
        }
    } else {               // W2 half (j-2): rows [0,128), k c8*128 + (j-2)*64 + [0,64)
        const int kh = j - 2;
#pragma unroll
        for (int c = tid; c < 128 * 8; c += 512) {
            int row = c >> 3, ch = c & 7;
            size_t g = (size_t)row * D_HID + c8 * 128 + kh * 64 + ch * 8;
            uint32_t o = toffW2(row, ch * 16);
            cp16(base + o,         g_w2t_hi + g);
            cp16(base + 16384 + o, g_w2t_lo + g);
        }
    }
    asm volatile("cp.async.commit_group;" ::: "memory");
}

__global__ __launch_bounds__(512, 1)
void fused_mlp_kernel(const float* __restrict__ b1, const float* __restrict__ b2,
                      float* __restrict__ out) {
    extern __shared__ char smem[];
    const uint32_t sb = smem_u32(smem);
    const int tid = threadIdx.x;
    const int lane = tid & 31;
    const int wid  = tid >> 5;           // 0..15
    const int wm1  = wid >> 1, wn1 = wid & 1;   // stage1: 8x2
    const int wm2  = wid >> 2, wn2 = wid & 3;   // stage2: 4x4
    const int row0 = blockIdx.x * 128;

    // prologue: start first two weight tiles before A conversion
    load_tile(smem, 0, 0);
    load_tile(smem, 1, 1);

    // ---- load A = h rows, fp32 -> bf16 hi/lo (plain stores) ----
    for (int c = tid; c < 128 * 16; c += 512) {
        int row = c >> 4, ch = c & 15;
        float4 f0 = make_float4(0.f, 0.f, 0.f, 0.f), f1 = f0;
        if (row0 + row < N_NODES) {
            const float* gp = g_h + (size_t)(row0 + row) * D_IN + ch * 8;
            f0 = *reinterpret_cast<const float4*>(gp);
            f1 = *reinterpret_cast<const float4*>(gp + 4);
        }
        uint4 vh, vl;
        vh.x = pack_bf2(f0.x, f0.y); vh.y = pack_bf2(f0.z, f0.w);
        vh.z = pack_bf2(f1.x, f1.y); vh.w = pack_bf2(f1.z, f1.w);
        vl.x = pack_bf2(f0.x - __bfloat162float(__float2bfloat16(f0.x)),
                        f0.y - __bfloat162float(__float2bfloat16(f0.y)));
        vl.y = pack_bf2(f0.z - __bfloat162float(__float2bfloat16(f0.z)),
                        f0.w - __bfloat162float(__float2bfloat16(f0.w)));
        vl.z = pack_bf2(f1.x - __bfloat162float(__float2bfloat16(f1.x)),
                        f1.y - __bfloat162float(__float2bfloat16(f1.y)));
        vl.w = pack_bf2(f1.z - __bfloat162float(__float2bfloat16(f1.z)),
                        f1.w - __bfloat162float(__float2bfloat16(f1.w)));
        uint32_t o = toff(row, ch * 16);
        *reinterpret_cast<uint4*>(smem + OFF_A_HI + o) = vh;
        *reinterpret_cast<uint4*>(smem + OFF_A_LO + o) = vl;
    }

    float oacc[2][4][4];
#pragma unroll
    for (int i = 0; i < 2; i++)
#pragma unroll
        for (int j = 0; j < 4; j++)
#pragma unroll
            for (int q = 0; q < 4; q++) oacc[i][j][q] = 0.f;

    for (int c8 = 0; c8 < 8; c8++) {
#pragma unroll
        for (int j = 0; j < 4; j++) {
            const int t = c8 * 4 + j;
            if (t == 31) asm volatile("cp.async.wait_group 0;" ::: "memory");
            else         asm volatile("cp.async.wait_group 1;" ::: "memory");
            __syncthreads();   // tile t resident; ring slot (t+2)%3 free; A/H ordered
            if (t + 2 < 32) load_tile(smem, t + 2, (t + 2) % 3);

            const uint32_t wb_hi = sb + OFF_WB + (t % 3) * 32768;
            const uint32_t wb_lo = wb_hi + 16384;

            if (j < 2) {
                // ---- stage 1 half j: 16x32 warp tile, hacc[4][4] ----
                float hacc[4][4];
#pragma unroll
                for (int n = 0; n < 4; n++)
#pragma unroll
                    for (int q = 0; q < 4; q++) hacc[n][q] = 0.f;

#pragma unroll
                for (int ks = 0; ks < 8; ks++) {
                    const int kb = ks * 32;
                    uint32_t ah[4], al[4];
                    {
                        int arow = wm1 * 16 + (lane & 15);
                        uint32_t off = toff(arow, kb + (lane >> 4) * 16);
                        ldsm_x4(ah, sb + OFF_A_HI + off);
                        ldsm_x4(al, sb + OFF_A_LO + off);
                    }
#pragma unroll
                    for (int p = 0; p < 2; p++) {
                        int brow = wn1 * 32 + p * 16 + (lane >> 4) * 8 + (lane & 7);
                        uint32_t off = toffW1(brow, kb + ((lane >> 3) & 1) * 16);
                        uint32_t bh[4], bl[4];
                        ldsm_x4(bh, wb_hi + off);
                        ldsm_x4(bl, wb_lo + off);
                        const int nt0 = p * 2;
                        mma_bf16(hacc[nt0],     ah, bh[0], bh[1]);
                        mma_bf16(hacc[nt0],     ah, bl[0], bl[1]);
                        mma_bf16(hacc[nt0],     al, bh[0], bh[1]);
                        mma_bf16(hacc[nt0 + 1], ah, bh[2], bh[3]);
                        mma_bf16(hacc[nt0 + 1], ah, bl[2], bl[3]);
                        mma_bf16(hacc[nt0 + 1], al, bh[2], bh[3]);
                    }
                }
                // ---- bias + relu + split this half -> H cols j*64+[0,64) ----
                {
                    int r = wm1 * 16 + (lane >> 2);
#pragma unroll
                    for (int nt = 0; nt < 4; nt++) {
                        int cl = j * 64 + wn1 * 32 + nt * 8 + (lane & 3) * 2;
                        float bv0 = __ldg(b1 + c8 * 128 + cl);
                        float bv1 = __ldg(b1 + c8 * 128 + cl + 1);
                        float x0 = fmaxf(hacc[nt][0] + bv0, 0.f);
                        float x1 = fmaxf(hacc[nt][1] + bv1, 0.f);
                        float x2 = fmaxf(hacc[nt][2] + bv0, 0.f);
                        float x3 = fmaxf(hacc[nt][3] + bv1, 0.f);
                        uint32_t o0 = toff(r,     cl * 2);
                        uint32_t o1 = toff(r + 8, cl * 2);
                        *reinterpret_cast<uint32_t*>(smem + OFF_H_HI + o0) = pack_bf2(x0, x1);
                        *reinterpret_cast<uint32_t*>(smem + OFF_H_LO + o0) =
                            pack_bf2(x0 - __bfloat162float(__float2bfloat16(x0)),
                                     x1 - __bfloat162float(__float2bfloat16(x1)));
                        *reinterpret_cast<uint32_t*>(smem + OFF_H_HI + o1) = pack_bf2(x2, x3);
                        *reinterpret_cast<uint32_t*>(smem + OFF_H_LO + o1) =
                            pack_bf2(x2 - __bfloat162float(__float2bfloat16(x2)),
                                     x3 - __bfloat162float(__float2bfloat16(x3)));
                    }
                }
            } else {
                // ---- stage 2 k-half (j-2): 32x32 warp tile ----
                const int kh = j - 2;
#pragma unroll
                for (int ks = 0; ks < 4; ks++) {
                    const int kbH = kh * 128 + ks * 32;
                    const int kbW = ks * 32;
                    uint32_t ah[2][4], al[2][4];
#pragma unroll
                    for (int mt = 0; mt < 2; mt++) {
                        int arow = wm2 * 32 + mt * 16 + (lane & 15);
                        uint32_t off = toff(arow, kbH + (lane >> 4) * 16);
                        ldsm_x4(ah[mt], sb + OFF_H_HI + off);
                        ldsm_x4(al[mt], sb + OFF_H_LO + off);
                    }
#pragma unroll
                    for (int p = 0; p < 2; p++) {
                        int brow = wn2 * 32 + p * 16 + (lane >> 4) * 8 + (lane & 7);
                        uint32_t off = toffW2(brow, kbW + ((lane >> 3) & 1) * 16);
                        uint32_t bh[4], bl[4];
                        ldsm_x4(bh, wb_hi + off);
                        ldsm_x4(bl, wb_lo + off);
#pragma unroll
                        for (int mt = 0; mt < 2; mt++) {
                            mma_bf16(oacc[mt][2 * p],     ah[mt], bh[0], bh[1]);
                            mma_bf16(oacc[mt][2 * p],     ah[mt], bl[0], bl[1]);
                            mma_bf16(oacc[mt][2 * p],     al[mt], bh[0], bh[1]);
                            mma_bf16(oacc[mt][2 * p + 1], ah[mt], bh[2], bh[3]);
                            mma_bf16(oacc[mt][2 * p + 1], ah[mt], bl[2], bl[3]);
                            mma_bf16(oacc[mt][2 * p + 1], al[mt], bh[2], bh[3]);
                        }
                    }
                }
            }
        }
    }

    // ---- final epilogue: out = oacc + b2 (stage2 layout) ----
#pragma unroll
    for (int mt = 0; mt < 2; mt++) {
        int r = row0 + wm2 * 32 + mt * 16 + (lane >> 2);
#pragma unroll
        for (int nt = 0; nt < 4; nt++) {
            int col = wn2 * 32 + nt * 8 + (lane & 3) * 2;
            float bv0 = __ldg(b2 + col), bv1 = __ldg(b2 + col + 1);
            if (r < N_NODES)
                *reinterpret_cast<float2*>(out + (size_t)r * D_OUT + col) =
                    make_float2(oacc[mt][nt][0] + bv0, oacc[mt][nt][1] + bv1);
            if (r + 8 < N_NODES)
                *reinterpret_cast<float2*>(out + (size_t)(r + 8) * D_OUT + col) =
                    make_float2(oacc[mt][nt][2] + bv0, oacc[mt][nt][3] + bv1);
        }
    }
}

// ---------------------------------------------------------------------------
// Launch: zero(0), scatter(1), wsplit(2), fusedMLP(3)  [index 3 gets profiled]
// ---------------------------------------------------------------------------
extern "C" void kernel_launch(void* const* d_in, const int* in_sizes, int n_in,
                              void* d_out, int out_size) {
    const float* feat = nullptr; const float* edge_feat = nullptr;
    const int*   src  = nullptr; const int*   dst = nullptr;
    const float* W1   = nullptr; const float* b1  = nullptr;
    const float* W2   = nullptr; const float* b2  = nullptr;

    for (int i = 0; i < n_in; i++) {
        long long sz = in_sizes[i];
        if      (sz == (long long)N_NODES * D_IN)  feat = (const float*)d_in[i];
        else if (sz == (long long)N_EDGES * D_IN)  edge_feat = (const float*)d_in[i];
        else if (sz == (long long)N_EDGES) { if (!src) src = (const int*)d_in[i]; else dst = (const int*)d_in[i]; }
        else if (sz == (long long)D_IN * D_HID) { if (!W1) W1 = (const float*)d_in[i]; else W2 = (const float*)d_in[i]; }
        else if (sz == (long long)D_HID)           b1 = (const float*)d_in[i];
        else if (sz == (long long)D_OUT)           b2 = (const float*)d_in[i];
    }
    float* out = (float*)d_out;

    constexpr int SMEM = 131072 + 3 * 32768;   // 224KB
    cudaFuncSetAttribute(fused_mlp_kernel, cudaFuncAttributeMaxDynamicSharedMemorySize, SMEM);

    { int n4 = N_NODES * D_IN / 4; zero_h_kernel<<<(n4 + 255) / 256, 256>>>(); }
    { int blocks = (N_EDGES + 7) / 8; scatter_kernel<<<blocks, 256>>>(feat, edge_feat, src, dst); }
    wsplit_kernel<<<1024, 256>>>(W1, W2);
    {
        dim3 grid((N_NODES + 127) / 128);
        fused_mlp_kernel<<<grid, 512, SMEM>>>(b1, b2, out);
    }
}

// round 11
// speedup vs baseline: 1.2143x; 1.2143x over previous
#include <cuda_runtime.h>
#include <cuda_fp16.h>
#include <cstdint>

#define N_NODES 50000
#define N_EDGES 600000
#define D_IN    128
#define D_HID   1024
#define D_OUT   128

// ---------------------------------------------------------------------------
// Device-global scratch. ONLY referenced from device code (host-shadow bug).
// Weights: single fp16 (2-term split needs only B-hi).
// ---------------------------------------------------------------------------
__device__ float  g_h[(size_t)N_NODES * D_IN];
__device__ __half g_w1t[(size_t)D_HID * D_IN];      // W1^T [1024][128] fp16
__device__ __half g_w2t[(size_t)D_OUT * D_HID];     // W2^T [128][1024] fp16

// ---------------------------------------------------------------------------
// Helpers
// ---------------------------------------------------------------------------
__device__ __forceinline__ uint32_t smem_u32(const void* p) {
    uint32_t a;
    asm("{ .reg .u64 t; cvta.to.shared.u64 t, %1; cvt.u32.u64 %0, t; }" : "=r"(a) : "l"(p));
    return a;
}
#define SW128(x) ((x) ^ (((x) >> 3) & 0x70))

// 128-row x 128-k tile: two 16KB sub-tiles (k-bytes [0,128),[128,256)), SW128.
__device__ __forceinline__ uint32_t toff(int row, int kbyte) {
    uint32_t w = (uint32_t)(row * 128 + (kbyte & 127));
    return (uint32_t)((kbyte >> 7) * 16384) + SW128(w);
}
// W1 half-tile: 64 rows x 128 k fp16 -> two 8KB sub-tiles.
__device__ __forceinline__ uint32_t toffW1(int row, int kbyte) {
    uint32_t w = (uint32_t)(row * 128 + (kbyte & 127));
    return (uint32_t)((kbyte >> 7) * 8192) + SW128(w);
}
// W2 half-tile: 128 rows x 64 k fp16 -> one 16KB tile (128B per row).
__device__ __forceinline__ uint32_t toffW2(int row, int kbyte) {
    uint32_t w = (uint32_t)(row * 128 + kbyte);
    return SW128(w);
}

__device__ __forceinline__ void ldsm_x4(uint32_t (&r)[4], uint32_t addr) {
    asm volatile("ldmatrix.sync.aligned.m8n8.x4.shared.b16 {%0,%1,%2,%3}, [%4];"
                 : "=r"(r[0]), "=r"(r[1]), "=r"(r[2]), "=r"(r[3]) : "r"(addr));
}
__device__ __forceinline__ void mma_f16(float (&d)[4], const uint32_t (&a)[4],
                                        uint32_t b0, uint32_t b1) {
    asm volatile(
        "mma.sync.aligned.m16n8k16.row.col.f32.f16.f16.f32 "
        "{%0,%1,%2,%3}, {%4,%5,%6,%7}, {%8,%9}, {%0,%1,%2,%3};"
        : "+f"(d[0]), "+f"(d[1]), "+f"(d[2]), "+f"(d[3])
        : "r"(a[0]), "r"(a[1]), "r"(a[2]), "r"(a[3]), "r"(b0), "r"(b1));
}
__device__ __forceinline__ uint32_t pack_h2(float x0, float x1) {
    __half2 p = __floats2half2_rn(x0, x1);
    return *reinterpret_cast<uint32_t*>(&p);
}
__device__ __forceinline__ float h_res(float x) {   // residual after fp16 round
    return x - __half2float(__float2half(x));
}
__device__ __forceinline__ void cp16(uint32_t dst, const void* src) {
    asm volatile("cp.async.cg.shared.global [%0], [%1], 16;" :: "r"(dst), "l"(src));
}

// ---------------------------------------------------------------------------
// Phase 1: zero accumulator
// ---------------------------------------------------------------------------
__global__ void zero_h_kernel() {
    int i = blockIdx.x * blockDim.x + threadIdx.x;
    const int n4 = N_NODES * D_IN / 4;
    if (i < n4) reinterpret_cast<float4*>(g_h)[i] = make_float4(0.f, 0.f, 0.f, 0.f);
}

// ---------------------------------------------------------------------------
// Phase 2: scatter (proven). One warp per edge; float4 atomics.
// ---------------------------------------------------------------------------
__global__ void scatter_kernel(const float* __restrict__ feat,
                               const float* __restrict__ edge_feat,
                               const int*   __restrict__ src,
                               const int*   __restrict__ dst) {
    int warp = (blockIdx.x * blockDim.x + threadIdx.x) >> 5;
    int lane = threadIdx.x & 31;
    if (warp >= N_EDGES) return;
    int s = src[warp], d = dst[warp];
    const float4 a = reinterpret_cast<const float4*>(feat      + (size_t)s    * D_IN)[lane];
    const float4 b = reinterpret_cast<const float4*>(edge_feat + (size_t)warp * D_IN)[lane];
    float4 m = make_float4(a.x + b.x, a.y + b.y, a.z + b.z, a.w + b.w);
    atomicAdd(reinterpret_cast<float4*>(g_h + (size_t)d * D_IN + lane * 4), m);
}

// ---------------------------------------------------------------------------
// Phase 3: weight transpose to single fp16 (one launch).
// ---------------------------------------------------------------------------
__global__ void wsplit_kernel(const float* __restrict__ W1, const float* __restrict__ W2) {
    int b = blockIdx.x;
    if (b < 512) {
        int i = b * 256 + threadIdx.x;               // over W1 [128][1024]
        int k = i >> 10, n = i & 1023;
        g_w1t[(size_t)n * D_IN + k] = __float2half(W1[i]);
    } else {
        int i = (b - 512) * 256 + threadIdx.x;       // over W2 [1024][128]
        int k = i >> 7, n = i & 127;
        g_w2t[(size_t)n * D_HID + k] = __float2half(W2[i]);
    }
}

// ---------------------------------------------------------------------------
// Phase 4: cp.async-pipelined fused MLP, fp16 2-term split.
// D = Ahi*B + Alo*B  (A,H: fp16 hi+lo; W: single fp16)
// Smem: A(64K) + H(64K) + 3x16K weight ring = 176KB, 1 CTA/SM, 512 threads.
// ---------------------------------------------------------------------------
#define OFF_A_HI 0
#define OFF_A_LO 32768
#define OFF_H_HI 65536
#define OFF_H_LO 98304
#define OFF_WB   131072      // 3 buffers x 16KB

__device__ __forceinline__ void load_tile(char* smem, int t, int wq) {
    const int c8 = t >> 2, j = t & 3;
    const int tid = threadIdx.x;
    const uint32_t base = smem_u32(smem) + OFF_WB + wq * 16384;
    if (j < 2) {           // W1 half j: rows c8*128 + j*64 + [0,64), k [0,128)
#pragma unroll
        for (int c = tid; c < 64 * 16; c += 512) {
            int row = c >> 4, ch = c & 15;
            size_t g = (size_t)(c8 * 128 + j * 64 + row) * D_IN + ch * 8;
            cp16(base + toffW1(row, ch * 16), g_w1t + g);
        }
    } else {               // W2 half (j-2): rows [0,128), k c8*128 + (j-2)*64 + [0,64)
        const int kh = j - 2;
#pragma unroll
        for (int c = tid; c < 128 * 8; c += 512) {
            int row = c >> 3, ch = c & 7;
            size_t g = (size_t)row * D_HID + c8 * 128 + kh * 64 + ch * 8;
            cp16(base + toffW2(row, ch * 16), g_w2t + g);
        }
    }
    asm volatile("cp.async.commit_group;" ::: "memory");
}

__global__ __launch_bounds__(512, 1)
void fused_mlp_kernel(const float* __restrict__ b1, const float* __restrict__ b2,
                      float* __restrict__ out) {
    extern __shared__ char smem[];
    const uint32_t sb = smem_u32(smem);
    const int tid = threadIdx.x;
    const int lane = tid & 31;
    const int wid  = tid >> 5;           // 0..15
    const int wm1  = wid >> 1, wn1 = wid & 1;   // stage1: 8x2, tile 16x32
    const int wm2  = wid >> 2, wn2 = wid & 3;   // stage2: 4x4, tile 32x32
    const int row0 = blockIdx.x * 128;

    // prologue: start first two weight tiles before A conversion
    load_tile(smem, 0, 0);
    load_tile(smem, 1, 1);

    // ---- load A = h rows, fp32 -> fp16 hi/lo ----
    for (int c = tid; c < 128 * 16; c += 512) {
        int row = c >> 4, ch = c & 15;
        float4 f0 = make_float4(0.f, 0.f, 0.f, 0.f), f1 = f0;
        if (row0 + row < N_NODES) {
            const float* gp = g_h + (size_t)(row0 + row) * D_IN + ch * 8;
            f0 = *reinterpret_cast<const float4*>(gp);
            f1 = *reinterpret_cast<const float4*>(gp + 4);
        }
        uint4 vh, vl;
        vh.x = pack_h2(f0.x, f0.y); vh.y = pack_h2(f0.z, f0.w);
        vh.z = pack_h2(f1.x, f1.y); vh.w = pack_h2(f1.z, f1.w);
        vl.x = pack_h2(h_res(f0.x), h_res(f0.y));
        vl.y = pack_h2(h_res(f0.z), h_res(f0.w));
        vl.z = pack_h2(h_res(f1.x), h_res(f1.y));
        vl.w = pack_h2(h_res(f1.z), h_res(f1.w));
        uint32_t o = toff(row, ch * 16);
        *reinterpret_cast<uint4*>(smem + OFF_A_HI + o) = vh;
        *reinterpret_cast<uint4*>(smem + OFF_A_LO + o) = vl;
    }

    float oacc[2][4][4];
#pragma unroll
    for (int i = 0; i < 2; i++)
#pragma unroll
        for (int j = 0; j < 4; j++)
#pragma unroll
            for (int q = 0; q < 4; q++) oacc[i][j][q] = 0.f;

    for (int c8 = 0; c8 < 8; c8++) {
#pragma unroll
        for (int j = 0; j < 4; j++) {
            const int t = c8 * 4 + j;
            if (t == 31) asm volatile("cp.async.wait_group 0;" ::: "memory");
            else         asm volatile("cp.async.wait_group 1;" ::: "memory");
            __syncthreads();   // tile t resident; ring slot (t+2)%3 free; A/H ordered
            if (t + 2 < 32) load_tile(smem, t + 2, (t + 2) % 3);

            const uint32_t wb = sb + OFF_WB + (t % 3) * 16384;

            if (j < 2) {
                // ---- stage 1 half j: 16x32 warp tile, 2-term ----
                float hacc[4][4];
#pragma unroll
                for (int n = 0; n < 4; n++)
#pragma unroll
                    for (int q = 0; q < 4; q++) hacc[n][q] = 0.f;

#pragma unroll
                for (int ks = 0; ks < 8; ks++) {
                    const int kb = ks * 32;
                    uint32_t ah[4], al[4];
                    {
                        int arow = wm1 * 16 + (lane & 15);
                        uint32_t off = toff(arow, kb + (lane >> 4) * 16);
                        ldsm_x4(ah, sb + OFF_A_HI + off);
                        ldsm_x4(al, sb + OFF_A_LO + off);
                    }
#pragma unroll
                    for (int p = 0; p < 2; p++) {
                        int brow = wn1 * 32 + p * 16 + (lane >> 4) * 8 + (lane & 7);
                        uint32_t bh[4];
                        ldsm_x4(bh, wb + toffW1(brow, kb + ((lane >> 3) & 1) * 16));
                        const int nt0 = p * 2;
                        mma_f16(hacc[nt0],     ah, bh[0], bh[1]);
                        mma_f16(hacc[nt0],     al, bh[0], bh[1]);
                        mma_f16(hacc[nt0 + 1], ah, bh[2], bh[3]);
                        mma_f16(hacc[nt0 + 1], al, bh[2], bh[3]);
                    }
                }
                // ---- bias + relu + fp16 split this half -> H cols j*64+[0,64) ----
                {
                    int r = wm1 * 16 + (lane >> 2);
#pragma unroll
                    for (int nt = 0; nt < 4; nt++) {
                        int cl = j * 64 + wn1 * 32 + nt * 8 + (lane & 3) * 2;
                        float bv0 = __ldg(b1 + c8 * 128 + cl);
                        float bv1 = __ldg(b1 + c8 * 128 + cl + 1);
                        float x0 = fmaxf(hacc[nt][0] + bv0, 0.f);
                        float x1 = fmaxf(hacc[nt][1] + bv1, 0.f);
                        float x2 = fmaxf(hacc[nt][2] + bv0, 0.f);
                        float x3 = fmaxf(hacc[nt][3] + bv1, 0.f);
                        uint32_t o0 = toff(r,     cl * 2);
                        uint32_t o1 = toff(r + 8, cl * 2);
                        *reinterpret_cast<uint32_t*>(smem + OFF_H_HI + o0) = pack_h2(x0, x1);
                        *reinterpret_cast<uint32_t*>(smem + OFF_H_LO + o0) =
                            pack_h2(h_res(x0), h_res(x1));
                        *reinterpret_cast<uint32_t*>(smem + OFF_H_HI + o1) = pack_h2(x2, x3);
                        *reinterpret_cast<uint32_t*>(smem + OFF_H_LO + o1) =
                            pack_h2(h_res(x2), h_res(x3));
                    }
                }
            } else {
                // ---- stage 2 k-half (j-2): 32x32 warp tile, 2-term ----
                const int kh = j - 2;
#pragma unroll
                for (int ks = 0; ks < 4; ks++) {
                    const int kbH = kh * 128 + ks * 32;
                    const int kbW = ks * 32;
                    uint32_t ah[2][4], al[2][4];
#pragma unroll
                    for (int mt = 0; mt < 2; mt++) {
                        int arow = wm2 * 32 + mt * 16 + (lane & 15);
                        uint32_t off = toff(arow, kbH + (lane >> 4) * 16);
                        ldsm_x4(ah[mt], sb + OFF_H_HI + off);
                        ldsm_x4(al[mt], sb + OFF_H_LO + off);
                    }
#pragma unroll
                    for (int p = 0; p < 2; p++) {
                        int brow = wn2 * 32 + p * 16 + (lane >> 4) * 8 + (lane & 7);
                        uint32_t bh[4];
                        ldsm_x4(bh, wb + toffW2(brow, kbW + ((lane >> 3) & 1) * 16));
#pragma unroll
                        for (int mt = 0; mt < 2; mt++) {
                            mma_f16(oacc[mt][2 * p],     ah[mt], bh[0], bh[1]);
                            mma_f16(oacc[mt][2 * p],     al[mt], bh[0], bh[1]);
                            mma_f16(oacc[mt][2 * p + 1], ah[mt], bh[2], bh[3]);
                            mma_f16(oacc[mt][2 * p + 1], al[mt], bh[2], bh[3]);
                        }
                    }
                }
            }
        }
    }

    // ---- final epilogue: out = oacc + b2 (stage2 layout) ----
#pragma unroll
    for (int mt = 0; mt < 2; mt++) {
        int r = row0 + wm2 * 32 + mt * 16 + (lane >> 2);
#pragma unroll
        for (int nt = 0; nt < 4; nt++) {
            int col = wn2 * 32 + nt * 8 + (lane & 3) * 2;
            float bv0 = __ldg(b2 + col), bv1 = __ldg(b2 + col + 1);
            if (r < N_NODES)
                *reinterpret_cast<float2*>(out + (size_t)r * D_OUT + col) =
                    make_float2(oacc[mt][nt][0] + bv0, oacc[mt][nt][1] + bv1);
            if (r + 8 < N_NODES)
                *reinterpret_cast<float2*>(out + (size_t)(r + 8) * D_OUT + col) =
                    make_float2(oacc[mt][nt][2] + bv0, oacc[mt][nt][3] + bv1);
        }
    }
}

// ---------------------------------------------------------------------------
// Launch: zero(0), scatter(1), wsplit(2), fusedMLP(3)
// ---------------------------------------------------------------------------
extern "C" void kernel_launch(void* const* d_in, const int* in_sizes, int n_in,
                              void* d_out, int out_size) {
    const float* feat = nullptr; const float* edge_feat = nullptr;
    const int*   src  = nullptr; const int*   dst = nullptr;
    const float* W1   = nullptr; const float* b1  = nullptr;
    const float* W2   = nullptr; const float* b2  = nullptr;

    for (int i = 0; i < n_in; i++) {
        long long sz = in_sizes[i];
        if      (sz == (long long)N_NODES * D_IN)  feat = (const float*)d_in[i];
        else if (sz == (long long)N_EDGES * D_IN)  edge_feat = (const float*)d_in[i];
        else if (sz == (long long)N_EDGES) { if (!src) src = (const int*)d_in[i]; else dst = (const int*)d_in[i]; }
        else if (sz == (long long)D_IN * D_HID) { if (!W1) W1 = (const float*)d_in[i]; else W2 = (const float*)d_in[i]; }
        else if (sz == (long long)D_HID)           b1 = (const float*)d_in[i];
        else if (sz == (long long)D_OUT)           b2 = (const float*)d_in[i];
    }
    float* out = (float*)d_out;

    constexpr int SMEM = 131072 + 3 * 16384;   // 180224 B = 176KB
    cudaFuncSetAttribute(fused_mlp_kernel, cudaFuncAttributeMaxDynamicSharedMemorySize, SMEM);

    { int n4 = N_NODES * D_IN / 4; zero_h_kernel<<<(n4 + 255) / 256, 256>>>(); }
    { int blocks = (N_EDGES + 7) / 8; scatter_kernel<<<blocks, 256>>>(feat, edge_feat, src, dst); }
    wsplit_kernel<<<1024, 256>>>(W1, W2);
    {
        dim3 grid((N_NODES + 127) / 128);
        fused_mlp_kernel<<<grid, 512, SMEM>>>(b1, b2, out);
    }
}

// round 12
// speedup vs baseline: 1.4901x; 1.2270x over previous
#include <cuda_runtime.h>
#include <cuda_fp16.h>
#include <cstdint>

#define N_NODES 50000
#define N_EDGES 600000
#define D_IN    128
#define D_HID   1024
#define D_OUT   128

// ---------------------------------------------------------------------------
// Device-global scratch. ONLY referenced from device code (host-shadow bug).
// ---------------------------------------------------------------------------
__device__ float  g_h[(size_t)N_NODES * D_IN];
__device__ __half g_w1t[(size_t)D_HID * D_IN];      // W1^T [1024][128] fp16
__device__ __half g_w2t[(size_t)D_OUT * D_HID];     // W2^T [128][1024] fp16

// ---------------------------------------------------------------------------
// Helpers
// ---------------------------------------------------------------------------
__device__ __forceinline__ uint32_t smem_u32(const void* p) {
    uint32_t a;
    asm("{ .reg .u64 t; cvta.to.shared.u64 t, %1; cvt.u32.u64 %0, t; }" : "=r"(a) : "l"(p));
    return a;
}
#define SW128(x) ((x) ^ (((x) >> 3) & 0x70))

// 128-row x 128-k fp16 tile: two 16KB sub-tiles (k-bytes [0,128),[128,256)), SW128.
__device__ __forceinline__ uint32_t toff(int row, int kbyte) {
    uint32_t w = (uint32_t)(row * 128 + (kbyte & 127));
    return (uint32_t)((kbyte >> 7) * 16384) + SW128(w);
}

__device__ __forceinline__ void ldsm_x4(uint32_t (&r)[4], uint32_t addr) {
    asm volatile("ldmatrix.sync.aligned.m8n8.x4.shared.b16 {%0,%1,%2,%3}, [%4];"
                 : "=r"(r[0]), "=r"(r[1]), "=r"(r[2]), "=r"(r[3]) : "r"(addr));
}
__device__ __forceinline__ void mma_f16(float (&d)[4], const uint32_t (&a)[4],
                                        uint32_t b0, uint32_t b1) {
    asm volatile(
        "mma.sync.aligned.m16n8k16.row.col.f32.f16.f16.f32 "
        "{%0,%1,%2,%3}, {%4,%5,%6,%7}, {%8,%9}, {%0,%1,%2,%3};"
        : "+f"(d[0]), "+f"(d[1]), "+f"(d[2]), "+f"(d[3])
        : "r"(a[0]), "r"(a[1]), "r"(a[2]), "r"(a[3]), "r"(b0), "r"(b1));
}
__device__ __forceinline__ uint32_t pack_h2(float x0, float x1) {
    __half2 p = __floats2half2_rn(x0, x1);
    return *reinterpret_cast<uint32_t*>(&p);
}
__device__ __forceinline__ void cp16(uint32_t dst, const void* src) {
    asm volatile("cp.async.cg.shared.global [%0], [%1], 16;" :: "r"(dst), "l"(src));
}

// ---------------------------------------------------------------------------
// Phase 1: zero accumulator
// ---------------------------------------------------------------------------
__global__ void zero_h_kernel() {
    int i = blockIdx.x * blockDim.x + threadIdx.x;
    const int n4 = N_NODES * D_IN / 4;
    if (i < n4) reinterpret_cast<float4*>(g_h)[i] = make_float4(0.f, 0.f, 0.f, 0.f);
}

// ---------------------------------------------------------------------------
// Phase 2: scatter (proven). One warp per edge; float4 atomics.
// ---------------------------------------------------------------------------
__global__ void scatter_kernel(const float* __restrict__ feat,
                               const float* __restrict__ edge_feat,
                               const int*   __restrict__ src,
                               const int*   __restrict__ dst) {
    int warp = (blockIdx.x * blockDim.x + threadIdx.x) >> 5;
    int lane = threadIdx.x & 31;
    if (warp >= N_EDGES) return;
    int s = src[warp], d = dst[warp];
    const float4 a = reinterpret_cast<const float4*>(feat      + (size_t)s    * D_IN)[lane];
    const float4 b = reinterpret_cast<const float4*>(edge_feat + (size_t)warp * D_IN)[lane];
    float4 m = make_float4(a.x + b.x, a.y + b.y, a.z + b.z, a.w + b.w);
    atomicAdd(reinterpret_cast<float4*>(g_h + (size_t)d * D_IN + lane * 4), m);
}

// ---------------------------------------------------------------------------
// Phase 3: weight transpose to fp16 (one launch).
// ---------------------------------------------------------------------------
__global__ void wsplit_kernel(const float* __restrict__ W1, const float* __restrict__ W2) {
    int b = blockIdx.x;
    if (b < 512) {
        int i = b * 256 + threadIdx.x;               // over W1 [128][1024]
        int k = i >> 10, n = i & 1023;
        g_w1t[(size_t)n * D_IN + k] = __float2half(W1[i]);
    } else {
        int i = (b - 512) * 256 + threadIdx.x;       // over W2 [1024][128]
        int k = i >> 7, n = i & 127;
        g_w2t[(size_t)n * D_HID + k] = __float2half(W2[i]);
    }
}

// ---------------------------------------------------------------------------
// Phase 4: cp.async-pipelined fused MLP, plain fp16 (1-term).
// Per chunk c8: tile t=2*c8 (W1c full 128x128) -> stage1 -> H;
//              tile t=2*c8+1 (W2c full 128x128) -> stage2 accumulate.
// Smem: A(32K) + H(32K) + 3x32K weight ring = 160KB, 1 CTA/SM, 512 threads.
// Stage1 warps 8(M)x2(N), tile 16x64. Stage2 warps 4(M)x4(N), tile 32x32.
// ---------------------------------------------------------------------------
#define OFF_A  0
#define OFF_H  32768
#define OFF_WB 65536      // 3 buffers x 32KB

__device__ __forceinline__ void load_tile(char* smem, int t, int wq) {
    const int c8 = t >> 1, j = t & 1;
    const int tid = threadIdx.x;
    const uint32_t base = smem_u32(smem) + OFF_WB + wq * 32768;
    if (j == 0) {          // W1 chunk: rows c8*128 + [0,128), k [0,128)
#pragma unroll
        for (int c = tid; c < 128 * 16; c += 512) {
            int row = c >> 4, ch = c & 15;
            size_t g = (size_t)(c8 * 128 + row) * D_IN + ch * 8;
            cp16(base + toff(row, ch * 16), g_w1t + g);
        }
    } else {               // W2 chunk: rows [0,128) n, k cols c8*128 + [0,128)
#pragma unroll
        for (int c = tid; c < 128 * 16; c += 512) {
            int row = c >> 4, ch = c & 15;
            size_t g = (size_t)row * D_HID + c8 * 128 + ch * 8;
            cp16(base + toff(row, ch * 16), g_w2t + g);
        }
    }
    asm volatile("cp.async.commit_group;" ::: "memory");
}

__global__ __launch_bounds__(512, 1)
void fused_mlp_kernel(const float* __restrict__ b1, const float* __restrict__ b2,
                      float* __restrict__ out) {
    extern __shared__ char smem[];
    const uint32_t sb = smem_u32(smem);
    const int tid = threadIdx.x;
    const int lane = tid & 31;
    const int wid  = tid >> 5;                  // 0..15
    const int wm1  = wid >> 1, wn1 = wid & 1;   // stage1: 8x2, tile 16x64
    const int wm2  = wid >> 2, wn2 = wid & 3;   // stage2: 4x4, tile 32x32
    const int row0 = blockIdx.x * 128;

    // prologue: prefetch first two weight tiles
    load_tile(smem, 0, 0);
    load_tile(smem, 1, 1);

    // ---- load A = h rows, fp32 -> fp16 ----
    for (int c = tid; c < 128 * 16; c += 512) {
        int row = c >> 4, ch = c & 15;
        float4 f0 = make_float4(0.f, 0.f, 0.f, 0.f), f1 = f0;
        if (row0 + row < N_NODES) {
            const float* gp = g_h + (size_t)(row0 + row) * D_IN + ch * 8;
            f0 = *reinterpret_cast<const float4*>(gp);
            f1 = *reinterpret_cast<const float4*>(gp + 4);
        }
        uint4 v;
        v.x = pack_h2(f0.x, f0.y); v.y = pack_h2(f0.z, f0.w);
        v.z = pack_h2(f1.x, f1.y); v.w = pack_h2(f1.z, f1.w);
        *reinterpret_cast<uint4*>(smem + OFF_A + toff(row, ch * 16)) = v;
    }

    float oacc[2][4][4];
#pragma unroll
    for (int i = 0; i < 2; i++)
#pragma unroll
        for (int j = 0; j < 4; j++)
#pragma unroll
            for (int q = 0; q < 4; q++) oacc[i][j][q] = 0.f;

    for (int c8 = 0; c8 < 8; c8++) {
#pragma unroll
        for (int j = 0; j < 2; j++) {
            const int t = c8 * 2 + j;
            if (t == 15) asm volatile("cp.async.wait_group 0;" ::: "memory");
            else         asm volatile("cp.async.wait_group 1;" ::: "memory");
            __syncthreads();   // tile t resident; ring slot (t+2)%3 free; H ordered
            if (t + 2 < 16) load_tile(smem, t + 2, (t + 2) % 3);

            const uint32_t wb = sb + OFF_WB + (t % 3) * 32768;

            if (j == 0) {
                // ---- stage 1: Hc = relu(A @ W1c + b1c), warp tile 16x64 ----
                float hacc[8][4];
#pragma unroll
                for (int n = 0; n < 8; n++)
#pragma unroll
                    for (int q = 0; q < 4; q++) hacc[n][q] = 0.f;

#pragma unroll
                for (int ks = 0; ks < 8; ks++) {
                    const int kb = ks * 32;
                    uint32_t a[4];
                    {
                        int arow = wm1 * 16 + (lane & 15);
                        ldsm_x4(a, sb + OFF_A + toff(arow, kb + (lane >> 4) * 16));
                    }
#pragma unroll
                    for (int p = 0; p < 4; p++) {
                        int brow = wn1 * 64 + p * 16 + (lane >> 4) * 8 + (lane & 7);
                        uint32_t bh[4];
                        ldsm_x4(bh, wb + toff(brow, kb + ((lane >> 3) & 1) * 16));
                        mma_f16(hacc[2 * p],     a, bh[0], bh[1]);
                        mma_f16(hacc[2 * p + 1], a, bh[2], bh[3]);
                    }
                }
                // ---- bias + relu -> H (fp16) ----
                {
                    int r = wm1 * 16 + (lane >> 2);
#pragma unroll
                    for (int nt = 0; nt < 8; nt++) {
                        int cl = wn1 * 64 + nt * 8 + (lane & 3) * 2;
                        float bv0 = __ldg(b1 + c8 * 128 + cl);
                        float bv1 = __ldg(b1 + c8 * 128 + cl + 1);
                        float x0 = fmaxf(hacc[nt][0] + bv0, 0.f);
                        float x1 = fmaxf(hacc[nt][1] + bv1, 0.f);
                        float x2 = fmaxf(hacc[nt][2] + bv0, 0.f);
                        float x3 = fmaxf(hacc[nt][3] + bv1, 0.f);
                        *reinterpret_cast<uint32_t*>(smem + OFF_H + toff(r,     cl * 2)) =
                            pack_h2(x0, x1);
                        *reinterpret_cast<uint32_t*>(smem + OFF_H + toff(r + 8, cl * 2)) =
                            pack_h2(x2, x3);
                    }
                }
            } else {
                // ---- stage 2: oacc += H @ W2c, warp tile 32x32 ----
#pragma unroll
                for (int ks = 0; ks < 8; ks++) {
                    const int kb = ks * 32;
                    uint32_t a[2][4];
#pragma unroll
                    for (int mt = 0; mt < 2; mt++) {
                        int arow = wm2 * 32 + mt * 16 + (lane & 15);
                        ldsm_x4(a[mt], sb + OFF_H + toff(arow, kb + (lane >> 4) * 16));
                    }
#pragma unroll
                    for (int p = 0; p < 2; p++) {
                        int brow = wn2 * 32 + p * 16 + (lane >> 4) * 8 + (lane & 7);
                        uint32_t bh[4];
                        ldsm_x4(bh, wb + toff(brow, kb + ((lane >> 3) & 1) * 16));
#pragma unroll
                        for (int mt = 0; mt < 2; mt++) {
                            mma_f16(oacc[mt][2 * p],     a[mt], bh[0], bh[1]);
                            mma_f16(oacc[mt][2 * p + 1], a[mt], bh[2], bh[3]);
                        }
                    }
                }
            }
        }
    }

    // ---- final epilogue: out = oacc + b2 (stage2 layout) ----
#pragma unroll
    for (int mt = 0; mt < 2; mt++) {
        int r = row0 + wm2 * 32 + mt * 16 + (lane >> 2);
#pragma unroll
        for (int nt = 0; nt < 4; nt++) {
            int col = wn2 * 32 + nt * 8 + (lane & 3) * 2;
            float bv0 = __ldg(b2 + col), bv1 = __ldg(b2 + col + 1);
            if (r < N_NODES)
                *reinterpret_cast<float2*>(out + (size_t)r * D_OUT + col) =
                    make_float2(oacc[mt][nt][0] + bv0, oacc[mt][nt][1] + bv1);
            if (r + 8 < N_NODES)
                *reinterpret_cast<float2*>(out + (size_t)(r + 8) * D_OUT + col) =
                    make_float2(oacc[mt][nt][2] + bv0, oacc[mt][nt][3] + bv1);
        }
    }
}

// ---------------------------------------------------------------------------
// Launch: zero(0), scatter(1), wsplit(2), fusedMLP(3)
// ---------------------------------------------------------------------------
extern "C" void kernel_launch(void* const* d_in, const int* in_sizes, int n_in,
                              void* d_out, int out_size) {
    const float* feat = nullptr; const float* edge_feat = nullptr;
    const int*   src  = nullptr; const int*   dst = nullptr;
    const float* W1   = nullptr; const float* b1  = nullptr;
    const float* W2   = nullptr; const float* b2  = nullptr;

    for (int i = 0; i < n_in; i++) {
        long long sz = in_sizes[i];
        if      (sz == (long long)N_NODES * D_IN)  feat = (const float*)d_in[i];
        else if (sz == (long long)N_EDGES * D_IN)  edge_feat = (const float*)d_in[i];
        else if (sz == (long long)N_EDGES) { if (!src) src = (const int*)d_in[i]; else dst = (const int*)d_in[i]; }
        else if (sz == (long long)D_IN * D_HID) { if (!W1) W1 = (const float*)d_in[i]; else W2 = (const float*)d_in[i]; }
        else if (sz == (long long)D_HID)           b1 = (const float*)d_in[i];
        else if (sz == (long long)D_OUT)           b2 = (const float*)d_in[i];
    }
    float* out = (float*)d_out;

    constexpr int SMEM = 65536 + 3 * 32768;   // 160KB
    cudaFuncSetAttribute(fused_mlp_kernel, cudaFuncAttributeMaxDynamicSharedMemorySize, SMEM);

    { int n4 = N_NODES * D_IN / 4; zero_h_kernel<<<(n4 + 255) / 256, 256>>>(); }
    { int blocks = (N_EDGES + 7) / 8; scatter_kernel<<<blocks, 256>>>(feat, edge_feat, src, dst); }
    wsplit_kernel<<<1024, 256>>>(W1, W2);
    {
        dim3 grid((N_NODES + 127) / 128);
        fused_mlp_kernel<<<grid, 512, SMEM>>>(b1, b2, out);
    }
}

// round 13
// speedup vs baseline: 1.5965x; 1.0714x over previous
#include <cuda_runtime.h>
#include <cuda_fp16.h>
#include <cstdint>

#define N_NODES 50000
#define N_EDGES 600000
#define D_IN    128
#define D_HID   1024
#define D_OUT   128

// ---------------------------------------------------------------------------
// Device-global scratch. ONLY referenced from device code (host-shadow bug).
// ---------------------------------------------------------------------------
__device__ float  g_h[(size_t)N_NODES * D_IN];
__device__ __half g_w1t[(size_t)D_HID * D_IN];      // W1^T [1024][128] fp16
__device__ __half g_w2t[(size_t)D_OUT * D_HID];     // W2^T [128][1024] fp16

// ---------------------------------------------------------------------------
// Helpers
// ---------------------------------------------------------------------------
__device__ __forceinline__ uint32_t smem_u32(const void* p) {
    uint32_t a;
    asm("{ .reg .u64 t; cvta.to.shared.u64 t, %1; cvt.u32.u64 %0, t; }" : "=r"(a) : "l"(p));
    return a;
}
#define SW128(x) ((x) ^ (((x) >> 3) & 0x70))

// 128-row x 128-k fp16 tile: two 16KB sub-tiles (k-bytes [0,128),[128,256)), SW128.
__device__ __forceinline__ uint32_t toff(int row, int kbyte) {
    uint32_t w = (uint32_t)(row * 128 + (kbyte & 127));
    return (uint32_t)((kbyte >> 7) * 16384) + SW128(w);
}

__device__ __forceinline__ void ldsm_x4(uint32_t (&r)[4], uint32_t addr) {
    asm volatile("ldmatrix.sync.aligned.m8n8.x4.shared.b16 {%0,%1,%2,%3}, [%4];"
                 : "=r"(r[0]), "=r"(r[1]), "=r"(r[2]), "=r"(r[3]) : "r"(addr));
}
__device__ __forceinline__ void mma_f16(float (&d)[4], const uint32_t (&a)[4],
                                        uint32_t b0, uint32_t b1) {
    asm volatile(
        "mma.sync.aligned.m16n8k16.row.col.f32.f16.f16.f32 "
        "{%0,%1,%2,%3}, {%4,%5,%6,%7}, {%8,%9}, {%0,%1,%2,%3};"
        : "+f"(d[0]), "+f"(d[1]), "+f"(d[2]), "+f"(d[3])
        : "r"(a[0]), "r"(a[1]), "r"(a[2]), "r"(a[3]), "r"(b0), "r"(b1));
}
__device__ __forceinline__ uint32_t pack_h2(float x0, float x1) {
    __half2 p = __floats2half2_rn(x0, x1);
    return *reinterpret_cast<uint32_t*>(&p);
}
__device__ __forceinline__ void cp16(uint32_t dst, const void* src) {
    asm volatile("cp.async.cg.shared.global [%0], [%1], 16;" :: "r"(dst), "l"(src));
}

// ---------------------------------------------------------------------------
// Phase 1: fused prelude — zero g_h + transpose weights to fp16.
// blocks [0,6250): zero; [6250,6762): W1; [6762,7274): W2.
// ---------------------------------------------------------------------------
__global__ void prelude_kernel(const float* __restrict__ W1, const float* __restrict__ W2) {
    int b = blockIdx.x;
    if (b < 6250) {
        int i = b * 256 + threadIdx.x;
        if (i < N_NODES * D_IN / 4)
            reinterpret_cast<float4*>(g_h)[i] = make_float4(0.f, 0.f, 0.f, 0.f);
    } else if (b < 6762) {
        int i = (b - 6250) * 256 + threadIdx.x;      // over W1 [128][1024]
        int k = i >> 10, n = i & 1023;
        g_w1t[(size_t)n * D_IN + k] = __float2half(W1[i]);
    } else {
        int i = (b - 6762) * 256 + threadIdx.x;      // over W2 [1024][128]
        int k = i >> 7, n = i & 127;
        g_w2t[(size_t)n * D_HID + k] = __float2half(W2[i]);
    }
}

// ---------------------------------------------------------------------------
// Phase 2: scatter (proven). One warp per edge; float4 atomics.
// ---------------------------------------------------------------------------
__global__ void scatter_kernel(const float* __restrict__ feat,
                               const float* __restrict__ edge_feat,
                               const int*   __restrict__ src,
                               const int*   __restrict__ dst) {
    int warp = (blockIdx.x * blockDim.x + threadIdx.x) >> 5;
    int lane = threadIdx.x & 31;
    if (warp >= N_EDGES) return;
    int s = src[warp], d = dst[warp];
    const float4 a = reinterpret_cast<const float4*>(feat      + (size_t)s    * D_IN)[lane];
    const float4 b = reinterpret_cast<const float4*>(edge_feat + (size_t)warp * D_IN)[lane];
    float4 m = make_float4(a.x + b.x, a.y + b.y, a.z + b.z, a.w + b.w);
    atomicAdd(reinterpret_cast<float4*>(g_h + (size_t)d * D_IN + lane * 4), m);
}

// ---------------------------------------------------------------------------
// Phase 3: fused MLP, fp16, merged-phase pipeline.
// Tiles t=2c (W1 chunk c), t=2c+1 (W2 chunk c); ring of 4 x 32KB slots.
// Phase p: stage2(p-1) [reads H[(p-1)&1], tile 2p-1] + stage1(p) [writes H[p&1],
// tile 2p]. One __syncthreads per phase. Smem: A 32K + H 2x32K + ring 128K = 224K.
// Both stages: 4(M)x4(N) warp grid, 32x32 warp tiles, 512 threads.
// ---------------------------------------------------------------------------
#define OFF_A  0
#define OFF_H  32768          // 2 buffers x 32KB
#define OFF_WB 98304          // 4 buffers x 32KB

__device__ __forceinline__ void load_tile(char* smem, int t) {
    const int c8 = t >> 1, j = t & 1;
    const int tid = threadIdx.x;
    const uint32_t base = smem_u32(smem) + OFF_WB + (t & 3) * 32768;
    if (j == 0) {          // W1 chunk: rows c8*128 + [0,128), k [0,128)
#pragma unroll
        for (int c = tid; c < 128 * 16; c += 512) {
            int row = c >> 4, ch = c & 15;
            size_t g = (size_t)(c8 * 128 + row) * D_IN + ch * 8;
            cp16(base + toff(row, ch * 16), g_w1t + g);
        }
    } else {               // W2 chunk: rows [0,128) n, k cols c8*128 + [0,128)
#pragma unroll
        for (int c = tid; c < 128 * 16; c += 512) {
            int row = c >> 4, ch = c & 15;
            size_t g = (size_t)row * D_HID + c8 * 128 + ch * 8;
            cp16(base + toff(row, ch * 16), g_w2t + g);
        }
    }
    asm volatile("cp.async.commit_group;" ::: "memory");
}

__global__ __launch_bounds__(512, 1)
void fused_mlp_kernel(const float* __restrict__ b1, const float* __restrict__ b2,
                      float* __restrict__ out) {
    extern __shared__ char smem[];
    const uint32_t sb = smem_u32(smem);
    const int tid = threadIdx.x;
    const int lane = tid & 31;
    const int wid  = tid >> 5;                 // 0..15
    const int wm   = wid >> 2, wn = wid & 3;   // 4x4 grid, 32x32 warp tiles
    const int row0 = blockIdx.x * 128;

    // prologue: prefetch tiles 0,1,2
    load_tile(smem, 0);
    load_tile(smem, 1);
    load_tile(smem, 2);

    // ---- load A = h rows, fp32 -> fp16 ----
    for (int c = tid; c < 128 * 16; c += 512) {
        int row = c >> 4, ch = c & 15;
        float4 f0 = make_float4(0.f, 0.f, 0.f, 0.f), f1 = f0;
        if (row0 + row < N_NODES) {
            const float* gp = g_h + (size_t)(row0 + row) * D_IN + ch * 8;
            f0 = *reinterpret_cast<const float4*>(gp);
            f1 = *reinterpret_cast<const float4*>(gp + 4);
        }
        uint4 v;
        v.x = pack_h2(f0.x, f0.y); v.y = pack_h2(f0.z, f0.w);
        v.z = pack_h2(f1.x, f1.y); v.w = pack_h2(f1.z, f1.w);
        *reinterpret_cast<uint4*>(smem + OFF_A + toff(row, ch * 16)) = v;
    }

    float oacc[2][4][4];
#pragma unroll
    for (int i = 0; i < 2; i++)
#pragma unroll
        for (int j = 0; j < 4; j++)
#pragma unroll
            for (int q = 0; q < 4; q++) oacc[i][j][q] = 0.f;

    for (int p = 0; p < 9; p++) {
        // all outstanding weight tiles (issued >= one phase ago) must have landed
        asm volatile("cp.async.wait_group 0;" ::: "memory");
        __syncthreads();   // H[p-1] visible; ring slots of phase p-1 free

        // issue tiles {2p+1, 2p+2} into slots freed by phase p-1
        if (p >= 1) {
            if (2 * p + 1 < 16) load_tile(smem, 2 * p + 1);
            if (2 * p + 2 < 16) load_tile(smem, 2 * p + 2);
        }

        // ---- stage 2 of chunk p-1: oacc += H[(p-1)&1] @ W2(p-1) ----
        if (p >= 1) {
            const uint32_t wb = sb + OFF_WB + ((2 * p - 1) & 3) * 32768;
            const uint32_t hb = sb + OFF_H + ((p - 1) & 1) * 32768;
#pragma unroll
            for (int ks = 0; ks < 8; ks++) {
                const int kb = ks * 32;
                uint32_t a[2][4];
#pragma unroll
                for (int mt = 0; mt < 2; mt++) {
                    int arow = wm * 32 + mt * 16 + (lane & 15);
                    ldsm_x4(a[mt], hb + toff(arow, kb + (lane >> 4) * 16));
                }
#pragma unroll
                for (int pn = 0; pn < 2; pn++) {
                    int brow = wn * 32 + pn * 16 + (lane >> 4) * 8 + (lane & 7);
                    uint32_t bh[4];
                    ldsm_x4(bh, wb + toff(brow, kb + ((lane >> 3) & 1) * 16));
#pragma unroll
                    for (int mt = 0; mt < 2; mt++) {
                        mma_f16(oacc[mt][2 * pn],     a[mt], bh[0], bh[1]);
                        mma_f16(oacc[mt][2 * pn + 1], a[mt], bh[2], bh[3]);
                    }
                }
            }
        }

        // ---- stage 1 of chunk p: H[p&1] = relu(A @ W1(p) + b1) ----
        if (p < 8) {
            const uint32_t wb = sb + OFF_WB + ((2 * p) & 3) * 32768;
            const uint32_t hb = sb + OFF_H + (p & 1) * 32768;
            float hacc[2][4][4];
#pragma unroll
            for (int i = 0; i < 2; i++)
#pragma unroll
                for (int j = 0; j < 4; j++)
#pragma unroll
                    for (int q = 0; q < 4; q++) hacc[i][j][q] = 0.f;

#pragma unroll
            for (int ks = 0; ks < 8; ks++) {
                const int kb = ks * 32;
                uint32_t a[2][4];
#pragma unroll
                for (int mt = 0; mt < 2; mt++) {
                    int arow = wm * 32 + mt * 16 + (lane & 15);
                    ldsm_x4(a[mt], sb + OFF_A + toff(arow, kb + (lane >> 4) * 16));
                }
#pragma unroll
                for (int pn = 0; pn < 2; pn++) {
                    int brow = wn * 32 + pn * 16 + (lane >> 4) * 8 + (lane & 7);
                    uint32_t bh[4];
                    ldsm_x4(bh, wb + toff(brow, kb + ((lane >> 3) & 1) * 16));
#pragma unroll
                    for (int mt = 0; mt < 2; mt++) {
                        mma_f16(hacc[mt][2 * pn],     a[mt], bh[0], bh[1]);
                        mma_f16(hacc[mt][2 * pn + 1], a[mt], bh[2], bh[3]);
                    }
                }
            }
            // bias + relu -> H[p&1] (fp16)
#pragma unroll
            for (int mt = 0; mt < 2; mt++) {
                int r = wm * 32 + mt * 16 + (lane >> 2);
#pragma unroll
                for (int j = 0; j < 4; j++) {
                    int cl = wn * 32 + j * 8 + (lane & 3) * 2;
                    float bv0 = __ldg(b1 + p * 128 + cl);
                    float bv1 = __ldg(b1 + p * 128 + cl + 1);
                    float x0 = fmaxf(hacc[mt][j][0] + bv0, 0.f);
                    float x1 = fmaxf(hacc[mt][j][1] + bv1, 0.f);
                    float x2 = fmaxf(hacc[mt][j][2] + bv0, 0.f);
                    float x3 = fmaxf(hacc[mt][j][3] + bv1, 0.f);
                    *reinterpret_cast<uint32_t*>(smem + OFF_H + (p & 1) * 32768 +
                                                 toff(r, cl * 2)) = pack_h2(x0, x1);
                    *reinterpret_cast<uint32_t*>(smem + OFF_H + (p & 1) * 32768 +
                                                 toff(r + 8, cl * 2)) = pack_h2(x2, x3);
                }
            }
        }
    }

    // ---- final epilogue: out = oacc + b2 ----
#pragma unroll
    for (int mt = 0; mt < 2; mt++) {
        int r = row0 + wm * 32 + mt * 16 + (lane >> 2);
#pragma unroll
        for (int nt = 0; nt < 4; nt++) {
            int col = wn * 32 + nt * 8 + (lane & 3) * 2;
            float bv0 = __ldg(b2 + col), bv1 = __ldg(b2 + col + 1);
            if (r < N_NODES)
                *reinterpret_cast<float2*>(out + (size_t)r * D_OUT + col) =
                    make_float2(oacc[mt][nt][0] + bv0, oacc[mt][nt][1] + bv1);
            if (r + 8 < N_NODES)
                *reinterpret_cast<float2*>(out + (size_t)(r + 8) * D_OUT + col) =
                    make_float2(oacc[mt][nt][2] + bv0, oacc[mt][nt][3] + bv1);
        }
    }
}

// ---------------------------------------------------------------------------
// Launch: prelude(0), scatter(1), fusedMLP(2)
// ---------------------------------------------------------------------------
extern "C" void kernel_launch(void* const* d_in, const int* in_sizes, int n_in,
                              void* d_out, int out_size) {
    const float* feat = nullptr; const float* edge_feat = nullptr;
    const int*   src  = nullptr; const int*   dst = nullptr;
    const float* W1   = nullptr; const float* b1  = nullptr;
    const float* W2   = nullptr; const float* b2  = nullptr;

    for (int i = 0; i < n_in; i++) {
        long long sz = in_sizes[i];
        if      (sz == (long long)N_NODES * D_IN)  feat = (const float*)d_in[i];
        else if (sz == (long long)N_EDGES * D_IN)  edge_feat = (const float*)d_in[i];
        else if (sz == (long long)N_EDGES) { if (!src) src = (const int*)d_in[i]; else dst = (const int*)d_in[i]; }
        else if (sz == (long long)D_IN * D_HID) { if (!W1) W1 = (const float*)d_in[i]; else W2 = (const float*)d_in[i]; }
        else if (sz == (long long)D_HID)           b1 = (const float*)d_in[i];
        else if (sz == (long long)D_OUT)           b2 = (const float*)d_in[i];
    }
    float* out = (float*)d_out;

    constexpr int SMEM = 98304 + 4 * 32768;   // 229376 B = 224KB
    cudaFuncSetAttribute(fused_mlp_kernel, cudaFuncAttributeMaxDynamicSharedMemorySize, SMEM);

    prelude_kernel<<<7274, 256>>>(W1, W2);
    { int blocks = (N_EDGES + 7) / 8; scatter_kernel<<<blocks, 256>>>(feat, edge_feat, src, dst); }
    {
        dim3 grid((N_NODES + 127) / 128);
        fused_mlp_kernel<<<grid, 512, SMEM>>>(b1, b2, out);
    }
}